// round 15
// baseline (speedup 1.0000x reference)
#include <cuda_runtime.h>

// VanillaSSM via exact diagonal recurrence (== reference FFT conv).
// When A_bar[d,:] is uniform in n (true here: log_A==0), all 64 states of a
// d are equal => y = K_d*u + D_d*x with ONE scalar recurrence per (b,d).
// Verified on-device; general scan is the else-branch of the SAME kernel.
//
// Fused fast path (single kernel, exact):
//   block (b,c) covers ALL 1024 d; thread owns 4 d via float4 (LDG/STG.128).
//   pass1: chunk end-state S_c from x, published via flag (last chunk skips)
//   seed:  spin on predecessor flags; u0 = Horner(a^CH, S_0..S_{c-1})
//   pass2: replay own chunk (L2-hot) and write y.
// C=32 chunks of 64 -> 256 blocks, 2/SM co-resident (296 cap) -> no deadlock.
// 8 outstanding LDG.128/warp -> ~8MB chip-wide in flight, 4x fewer LSU wf.

namespace {

constexpr int BATCH   = 8;
constexpr int L       = 2048;
constexpr int D_MODEL = 1024;
constexpr int NSTATE  = 64;
constexpr float DT    = 0.1f;

constexpr int C   = 32;          // chunks per sequence
constexpr int CH  = L / C;       // 64 steps per chunk
constexpr int BW  = 8;           // rows per load batch
constexpr int NBT = CH / BW;     // 8 batches
constexpr int RS4 = D_MODEL / 4; // row stride in float4

// ---------------- scratch (persistent; rewritten every launch) -----------
__device__ float g_K[D_MODEL];
__device__ float g_a[D_MODEL];
__device__ int   g_uni[64];
__device__ float g_S[BATCH * C * D_MODEL];      // chunk end-states (1 MB)
__device__ int   g_flag[BATCH * C];             // carry-ready flags (256)

// ---------------- packed f32x2 helpers (general fallback) ----------------
__device__ __forceinline__ unsigned long long pack2(float lo, float hi) {
    unsigned long long r;
    asm("mov.b64 %0, {%1, %2};" : "=l"(r) : "f"(lo), "f"(hi));
    return r;
}
__device__ __forceinline__ void unpack2(unsigned long long v, float& lo, float& hi) {
    asm("mov.b64 {%0, %1}, %2;" : "=f"(lo), "=f"(hi) : "l"(v));
}
__device__ __forceinline__ unsigned long long mul2(unsigned long long a, unsigned long long b) {
    unsigned long long r;
    asm("mul.rn.f32x2 %0, %1, %2;" : "=l"(r) : "l"(a), "l"(b));
    return r;
}
__device__ __forceinline__ unsigned long long fma2(unsigned long long a, unsigned long long b,
                                                   unsigned long long c) {
    unsigned long long r;
    asm("fma.rn.f32x2 %0, %1, %2, %3;" : "=l"(r) : "l"(a), "l"(b), "l"(c));
    return r;
}

__device__ __forceinline__ bool all_uniform() {
    const int4* p = (const int4*)g_uni;
    int u = 1;
#pragma unroll
    for (int i = 0; i < 16; ++i) {
        const int4 v = p[i];
        u &= v.x & v.y & v.z & v.w;
    }
    return u != 0;
}

// ================= setup: coefficients + uniformity + flag reset =========
// 64 blocks x 128 threads: 8 threads per d, 8 states per thread.
__global__ __launch_bounds__(128)
void ssm_setup_kernel(const float* __restrict__ log_A,
                      const float* __restrict__ Bp,
                      const float* __restrict__ Cp)
{
    __shared__ int s_uni;
    if (threadIdx.x == 0) s_uni = 1;
    __syncthreads();

    const int tid = threadIdx.x;
    if (blockIdx.x < 2) g_flag[blockIdx.x * 128 + tid] = 0;

    const int d    = blockIdx.x * 16 + (tid >> 3);
    const int n0   = (tid & 7) * 8;
    const int base = d * NSTATE + n0;

    const float4 la0 = *(const float4*)&log_A[base];
    const float4 la1 = *(const float4*)&log_A[base + 4];
    const float4 bp0 = *(const float4*)&Bp[base];
    const float4 bp1 = *(const float4*)&Bp[base + 4];
    const float4 cp0 = *(const float4*)&Cp[base];
    const float4 cp1 = *(const float4*)&Cp[base + 4];

    float la[8] = {la0.x, la0.y, la0.z, la0.w, la1.x, la1.y, la1.z, la1.w};
    float bp[8] = {bp0.x, bp0.y, bp0.z, bp0.w, bp1.x, bp1.y, bp1.z, bp1.w};
    float cp[8] = {cp0.x, cp0.y, cp0.z, cp0.w, cp1.x, cp1.y, cp1.z, cp1.w};

    float K = 0.0f, a[8];
    bool uni = true;
#pragma unroll
    for (int j = 0; j < 8; ++j) {
        const float A = -expf(la[j]);
        a[j] = expf(DT * A);
        K += (a[j] - 1.0f) / A * bp[j] * cp[j];
        uni = uni && (__float_as_int(a[j]) == __float_as_int(a[0]));
    }
    const float aref = __shfl_sync(0xFFFFFFFFu, a[0], (tid & 31) & ~7);
    uni = uni && (__float_as_int(a[0]) == __float_as_int(aref));

#pragma unroll
    for (int off = 1; off < 8; off <<= 1)
        K += __shfl_xor_sync(0xFFFFFFFFu, K, off);

    if ((tid & 7) == 0) { g_K[d] = K; g_a[d] = aref; }
    if (__ballot_sync(0xFFFFFFFFu, !uni) != 0) s_uni = 0;   // benign race
    __syncthreads();
    if (threadIdx.x == 0) g_uni[blockIdx.x] = s_uni;
}

// ================= fused scan: fast chunked path + general fallback ======
constexpr int T    = 32;
constexpr int NR   = L / T;
constexpr int XSTR = 40;

__global__ __launch_bounds__(256)
void ssm_fused_kernel(const float* __restrict__ x,
                      const float* __restrict__ log_A,
                      const float* __restrict__ Bp,
                      const float* __restrict__ Cp,
                      const float* __restrict__ Dp,
                      float* __restrict__ y)
{
    __shared__ float xs[8][2][4 * XSTR];    // general path only (10 KB)

    const int tid = threadIdx.x;
    const int bid = blockIdx.x;

    if (all_uniform()) {
        // -------- fast path: block (b,c), thread owns 4 d via float4 -----
        const int c = bid & (C - 1);
        const int b = bid >> 5;
        const int d = tid * 4;

        const float4 a4 = *(const float4*)&g_a[d];
        const float4 K4 = *(const float4*)&g_K[d];
        const float4 D4 = *(const float4*)&Dp[d];

        const float4* xc = (const float4*)(x + ((long)b * L + c * CH) * D_MODEL) + tid;
        float4*       yc = (float4*)(y + ((long)b * L + c * CH) * D_MODEL) + tid;

        float4 u = make_float4(0.f, 0.f, 0.f, 0.f);
        float4 buf0[BW], buf1[BW];

        // pass 1: own chunk end-state (skipped for last chunk: never used)
        if (c < C - 1) {
#pragma unroll
            for (int j = 0; j < BW; ++j) buf0[j] = xc[j * RS4];
#pragma unroll
            for (int bt = 0; bt < NBT; ++bt) {
                float4* cur = (bt & 1) ? buf1 : buf0;
                float4* nxt = (bt & 1) ? buf0 : buf1;
                if (bt + 1 < NBT) {
#pragma unroll
                    for (int j = 0; j < BW; ++j)
                        nxt[j] = xc[((bt + 1) * BW + j) * RS4];
                }
#pragma unroll
                for (int j = 0; j < BW; ++j) {
                    const float4 xv = cur[j];
                    u.x = fmaf(a4.x, u.x, xv.x);
                    u.y = fmaf(a4.y, u.y, xv.y);
                    u.z = fmaf(a4.z, u.z, xv.z);
                    u.w = fmaf(a4.w, u.w, xv.w);
                }
            }
            *(float4*)&g_S[(b * C + c) * D_MODEL + d] = u;
            __threadfence();
            __syncthreads();
            if (tid == 0)
                atomicExch(&g_flag[b * C + c], 1);
        }

        // a^CH via squarings (CH = 64 = 2^6)
        float4 ap = a4;
#pragma unroll
        for (int k = 0; k < 6; ++k) {
            ap.x *= ap.x; ap.y *= ap.y; ap.z *= ap.z; ap.w *= ap.w;
        }

        // wait for predecessors, then exact Horner seed
        u = make_float4(0.f, 0.f, 0.f, 0.f);
        if (c > 0) {
            if (tid < c) {
                while (atomicAdd(&g_flag[b * C + tid], 0) == 0)
                    __nanosleep(128);
                __threadfence();
            }
            __syncthreads();
            for (int j = 0; j < c; ++j) {
                const float4 S = *(const float4*)&g_S[(b * C + j) * D_MODEL + d];
                u.x = fmaf(ap.x, u.x, S.x);
                u.y = fmaf(ap.y, u.y, S.y);
                u.z = fmaf(ap.z, u.z, S.z);
                u.w = fmaf(ap.w, u.w, S.w);
            }
        }

        // pass 2: replay own chunk (L2-hot), write y
#pragma unroll
        for (int j = 0; j < BW; ++j) buf0[j] = xc[j * RS4];
#pragma unroll
        for (int bt = 0; bt < NBT; ++bt) {
            float4* cur = (bt & 1) ? buf1 : buf0;
            float4* nxt = (bt & 1) ? buf0 : buf1;
            if (bt + 1 < NBT) {
#pragma unroll
                for (int j = 0; j < BW; ++j)
                    nxt[j] = xc[((bt + 1) * BW + j) * RS4];
            }
#pragma unroll
            for (int j = 0; j < BW; ++j) {
                const float4 xv = cur[j];
                float4 o;
                u.x = fmaf(a4.x, u.x, xv.x);
                u.y = fmaf(a4.y, u.y, xv.y);
                u.z = fmaf(a4.z, u.z, xv.z);
                u.w = fmaf(a4.w, u.w, xv.w);
                o.x = fmaf(D4.x, xv.x, K4.x * u.x);
                o.y = fmaf(D4.y, xv.y, K4.y * u.y);
                o.z = fmaf(D4.z, xv.z, K4.z * u.z);
                o.w = fmaf(D4.w, xv.w, K4.w * u.w);
                yc[(bt * BW + j) * RS4] = o;
            }
        }
        return;
    }

    // ---------------- general fallback (R5 logic, 8 warps / 32 d per blk) -
    const int b     = bid >> 5;
    const int d0blk = (bid & 31) * 32;
    const int w     = tid >> 5;
    const int lane  = tid & 31;
    const int g     = lane >> 3;
    const int gl    = lane & 7;
    const int d0w   = d0blk + w * 4;
    const int d     = d0w + g;

    unsigned long long a01[4], k01[4];
    {
        const int cb = d * NSTATE + gl * 4;
        const float4 laL = *(const float4*)&log_A[cb];
        const float4 laH = *(const float4*)&log_A[cb + 32];
        const float4 bL  = *(const float4*)&Bp[cb];
        const float4 bH  = *(const float4*)&Bp[cb + 32];
        const float4 cL  = *(const float4*)&Cp[cb];
        const float4 cH  = *(const float4*)&Cp[cb + 32];
        const float* laLp = &laL.x; const float* laHp = &laH.x;
        const float* bLp  = &bL.x;  const float* bHp  = &bH.x;
        const float* cLp  = &cL.x;  const float* cHp  = &cH.x;
#pragma unroll
        for (int j = 0; j < 4; ++j) {
            const float AL = -expf(laLp[j]);
            const float AH = -expf(laHp[j]);
            const float aL = expf(DT * AL);
            const float aH = expf(DT * AH);
            a01[j] = pack2(aL, aH);
            k01[j] = pack2((aL - 1.0f) / AL * bLp[j] * cLp[j],
                           (aH - 1.0f) / AH * bHp[j] * cHp[j]);
        }
    }

    const int si = lane >> 2;
    const int sj = lane & 3;
    const float Dd = Dp[d0w + sj];
    const float* xg = x + (long)b * L * D_MODEL + d0w + sj;
    float*       yg = y + (long)b * L * D_MODEL + d0w + sj;

    float xpre[4], xcur[4];
#pragma unroll
    for (int k = 0; k < 4; ++k)
        xpre[k] = xg[(si + 8 * k) * D_MODEL];

    unsigned long long u0 = 0ull, u1 = 0ull, u2 = 0ull, u3 = 0ull;

    for (int r = 0; r < NR; ++r) {
        const int l0 = r * T;
        float* xb = xs[w][r & 1];
#pragma unroll
        for (int k = 0; k < 4; ++k) {
            xcur[k] = xpre[k];
            xb[sj * XSTR + si + 8 * k] = xpre[k];
        }
        __syncwarp();
        if (r + 1 < NR) {
#pragma unroll
            for (int k = 0; k < 4; ++k)
                xpre[k] = xg[(l0 + T + si + 8 * k) * D_MODEL];
        }

        float y_out[4];
#pragma unroll
        for (int tb = 0; tb < T; tb += 16) {
            float v[16];
#pragma unroll
            for (int q = 0; q < 16; q += 4) {
                const float4 xq = *(const float4*)&xb[g * XSTR + tb + q];
                const float* xe = &xq.x;
#pragma unroll
                for (int i2 = 0; i2 < 4; ++i2) {
                    const unsigned long long xx = pack2(xe[i2], xe[i2]);
                    u0 = fma2(a01[0], u0, xx);
                    u1 = fma2(a01[1], u1, xx);
                    u2 = fma2(a01[2], u2, xx);
                    u3 = fma2(a01[3], u3, xx);
                    unsigned long long acc = mul2(k01[0], u0);
                    acc = fma2(k01[1], u1, acc);
                    acc = fma2(k01[2], u2, acc);
                    float lo, hi;
                    unpack2(fma2(k01[3], u3, acc), lo, hi);
                    v[q + i2] = lo + hi;
                }
            }
            {
                const bool h4 = (gl & 4) != 0;
#pragma unroll
                for (int ii = 0; ii < 8; ++ii) {
                    const int i = (ii < 4) ? ii : ii + 4;
                    const float send = h4 ? v[i] : v[i + 4];
                    const float keep = h4 ? v[i + 4] : v[i];
                    v[i] = keep + __shfl_xor_sync(0xFFFFFFFFu, send, 4);
                }
                const bool h2 = (gl & 2) != 0;
#pragma unroll
                for (int ii = 0; ii < 4; ++ii) {
                    const int i = (ii < 2) ? ii : ii + 6;
                    const float send = h2 ? v[i] : v[i + 2];
                    const float keep = h2 ? v[i + 2] : v[i];
                    v[i] = keep + __shfl_xor_sync(0xFFFFFFFFu, send, 2);
                }
                const bool h1 = (gl & 1) != 0;
#pragma unroll
                for (int ii = 0; ii < 2; ++ii) {
                    const int i = ii * 8;
                    const float send = h1 ? v[i] : v[i + 1];
                    const float keep = h1 ? v[i + 1] : v[i];
                    v[i] = keep + __shfl_xor_sync(0xFFFFFFFFu, send, 1);
                }
            }
            const int srcLane = sj * 8 + si;
            y_out[tb / 8]     = __shfl_sync(0xFFFFFFFFu, v[0], srcLane);
            y_out[tb / 8 + 1] = __shfl_sync(0xFFFFFFFFu, v[8], srcLane);
        }
#pragma unroll
        for (int k = 0; k < 4; ++k)
            yg[(l0 + si + 8 * k) * D_MODEL] = fmaf(Dd, xcur[k], y_out[k]);
    }
}

} // namespace

extern "C" void kernel_launch(void* const* d_in, const int* in_sizes, int n_in,
                              void* d_out, int out_size)
{
    const float* x     = (const float*)d_in[0];
    const float* log_A = (const float*)d_in[1];
    const float* Bp    = (const float*)d_in[2];
    const float* Cp    = (const float*)d_in[3];
    const float* Dp    = (const float*)d_in[4];
    float* y           = (float*)d_out;

    ssm_setup_kernel<<<64, 128>>>(log_A, Bp, Cp);
    ssm_fused_kernel<<<C * BATCH, 256>>>(x, log_A, Bp, Cp, Dp, y);
}